// round 14
// baseline (speedup 1.0000x reference)
#include <cuda_runtime.h>
#include <cuda_bf16.h>
#include <cuda_fp16.h>
#include <cstdint>

#define NB 2
#define LD 4800
#define SD 4800
#define CD 256
#define TEMPER 0.1f
#define THRESH 0.2f
#define BORDER 2

#define KTOT 768          // A_cat=[hi|hi|lo], B_cat=[hi|lo|hi]
#define TM 128
#define TN 128
#define KC 64
#define NCHUNK (KTOT / KC)
#define ROWB 144
#define ABUF_B (TM * ROWB)
#define BBUF_B (TN * ROWB)
#define STG_B (ABUF_B + BBUF_B)
#define NSTG 3
#define DSMEM_B (NSTG * STG_B)

// ---------------- scratch ----------------
__device__ __half g_e[(size_t)NB * LD * SD];      // exp(2*sim) in fp16 (92 MB)
__device__ __align__(128) __nv_bfloat16 g_acat[(size_t)NB * LD * KTOT];
__device__ __align__(128) __nv_bfloat16 g_bcat[(size_t)NB * SD * KTOT];
__device__ float g_rsum[NB * LD];
__device__ float g_csum[NB * SD];
__device__ unsigned long long g_rkey[NB * LD];   // (conf_rowmax_bits<<32)|(0x7fffffff-idx)
__device__ int g_ccmax[NB * SD];                  // conf col max bits

// ---------------- PTX helpers ----------------
__device__ __forceinline__ uint32_t s2u(const void* p) {
    uint32_t a;
    asm("{ .reg .u64 t; cvta.to.shared.u64 t, %1; cvt.u32.u64 %0, t; }" : "=r"(a) : "l"(p));
    return a;
}
__device__ __forceinline__ void ldsm_x4(uint32_t& r0, uint32_t& r1, uint32_t& r2, uint32_t& r3,
                                        uint32_t addr) {
    asm volatile("ldmatrix.sync.aligned.m8n8.x4.shared.b16 {%0,%1,%2,%3}, [%4];"
                 : "=r"(r0), "=r"(r1), "=r"(r2), "=r"(r3) : "r"(addr));
}
__device__ __forceinline__ void mma_bf16(float* d, const uint32_t* a, const uint32_t* b) {
    asm volatile(
        "mma.sync.aligned.m16n8k16.row.col.f32.bf16.bf16.f32 "
        "{%0,%1,%2,%3}, {%4,%5,%6,%7}, {%8,%9}, {%0,%1,%2,%3};"
        : "+f"(d[0]), "+f"(d[1]), "+f"(d[2]), "+f"(d[3])
        : "r"(a[0]), "r"(a[1]), "r"(a[2]), "r"(a[3]), "r"(b[0]), "r"(b[1]));
}
__device__ __forceinline__ void cp16(uint32_t dst, const void* src, bool pred) {
    int sz = pred ? 16 : 0;
    asm volatile("cp.async.cg.shared.global [%0], [%1], 16, %2;"
                 :: "r"(dst), "l"(src), "r"(sz) : "memory");
}
#define CP_COMMIT() asm volatile("cp.async.commit_group;" ::: "memory")
#define CP_WAIT1()  asm volatile("cp.async.wait_group 1;" ::: "memory")
#define CP_WAIT0()  asm volatile("cp.async.wait_group 0;" ::: "memory")

// fp32x4 -> packed bf16 hi/lo pairs
__device__ __forceinline__ void split4(const float4& x, uint2& hp, uint2& lp) {
    __nv_bfloat16 h0 = __float2bfloat16(x.x), h1 = __float2bfloat16(x.y);
    __nv_bfloat16 h2 = __float2bfloat16(x.z), h3 = __float2bfloat16(x.w);
    __nv_bfloat16 l0 = __float2bfloat16(x.x - __bfloat162float(h0));
    __nv_bfloat16 l1 = __float2bfloat16(x.y - __bfloat162float(h1));
    __nv_bfloat16 l2 = __float2bfloat16(x.z - __bfloat162float(h2));
    __nv_bfloat16 l3 = __float2bfloat16(x.w - __bfloat162float(h3));
    __nv_bfloat162 a01 = __nv_bfloat162(h0, h1), a23 = __nv_bfloat162(h2, h3);
    __nv_bfloat162 b01 = __nv_bfloat162(l0, l1), b23 = __nv_bfloat162(l2, l3);
    hp.x = *reinterpret_cast<uint32_t*>(&a01); hp.y = *reinterpret_cast<uint32_t*>(&a23);
    lp.x = *reinterpret_cast<uint32_t*>(&b01); lp.y = *reinterpret_cast<uint32_t*>(&b23);
}

// ---------------- kernels ----------------
__global__ void k_init() {
    int i = blockIdx.x * blockDim.x + threadIdx.x;
    if (i < NB * SD) {
        g_rsum[i] = 0.f;
        g_csum[i] = 0.f;
        g_rkey[i] = 0ull;
        g_ccmax[i] = 0;
    }
}

// vectorized fp32 -> bf16 hi/lo packing
__global__ void __launch_bounds__(256) k_convert(const float* __restrict__ f0,
                                                 const float* __restrict__ f1) {
    int idx = blockIdx.x * blockDim.x + threadIdx.x;
    if (idx >= NB * LD * (CD / 4)) return;
    int row = idx / (CD / 4);
    int c = (idx % (CD / 4)) * 4;
    {
        float4 x = *reinterpret_cast<const float4*>(f0 + (size_t)row * CD + c);
        uint2 hp, lp; split4(x, hp, lp);
        __nv_bfloat16* r = g_acat + (size_t)row * KTOT;
        *reinterpret_cast<uint2*>(r + c) = hp;
        *reinterpret_cast<uint2*>(r + CD + c) = hp;
        *reinterpret_cast<uint2*>(r + 2 * CD + c) = lp;
    }
    {
        float4 x = *reinterpret_cast<const float4*>(f1 + (size_t)row * CD + c);
        uint2 hp, lp; split4(x, hp, lp);
        __nv_bfloat16* r = g_bcat + (size_t)row * KTOT;
        *reinterpret_cast<uint2*>(r + c) = hp;
        *reinterpret_cast<uint2*>(r + CD + c) = lp;
        *reinterpret_cast<uint2*>(r + 2 * CD + c) = hp;
    }
}

// HMMA bf16 GEMM 128x128 (one batch per launch) -> fp16 exp(2*sim) + fused stats
__global__ void __launch_bounds__(256, 2) k_gemm_mma(int b) {
    extern __shared__ char smem[];
    const int tid = threadIdx.x;
    const int wid = tid >> 5;
    const int lane = tid & 31;
    const int warp_m = wid & 1;
    const int warp_n = wid >> 1;

    const int m0 = blockIdx.y * TM;
    const int n0 = blockIdx.x * TN;
    const int mrem = min(TM, LD - m0);
    const int nrem = min(TN, SD - n0);

    const __nv_bfloat16* Abase = g_acat + (size_t)(b * LD + m0) * KTOT;
    const __nv_bfloat16* Bbase = g_bcat + (size_t)(b * SD + n0) * KTOT;
    const uint32_t sbase = s2u(smem);

    float acc[4][4][4];
    #pragma unroll
    for (int i = 0; i < 4; i++)
        #pragma unroll
        for (int j = 0; j < 4; j++)
            #pragma unroll
            for (int q = 0; q < 4; q++) acc[i][j][q] = 0.f;

    auto issue = [&](int chunk, int buf) {
        const int k0 = chunk * KC;
        const uint32_t sA = sbase + buf * STG_B;
        const uint32_t sB = sA + ABUF_B;
        #pragma unroll
        for (int i = 0; i < 4; i++) {
            int f = tid + i * 256;
            int row = f >> 3, q = f & 7;
            bool pa = row < mrem;
            int ra = pa ? row : 0;
            cp16(sA + row * ROWB + q * 16, Abase + (size_t)ra * KTOT + k0 + q * 8, pa);
            bool pb = row < nrem;
            int rb = pb ? row : 0;
            cp16(sB + row * ROWB + q * 16, Bbase + (size_t)rb * KTOT + k0 + q * 8, pb);
        }
        CP_COMMIT();
    };

    issue(0, 0);
    issue(1, 1);

    const int g = lane >> 3;
    const int lr = lane & 7;

    for (int s = 0; s < NCHUNK; s++) {
        if (s == NCHUNK - 1) { CP_WAIT0(); } else { CP_WAIT1(); }
        __syncthreads();
        const int buf = s % NSTG;
        const uint32_t sA = sbase + buf * STG_B;
        const uint32_t sB = sA + ABUF_B;
        if (s + 2 < NCHUNK) issue(s + 2, (s + 2) % NSTG);

        #pragma unroll
        for (int ks = 0; ks < KC / 16; ks++) {
            const int kb = ks * 16;
            uint32_t a[4][4];
            #pragma unroll
            for (int mi = 0; mi < 4; mi++) {
                uint32_t addr = sA + (uint32_t)((warp_m * 64 + mi * 16 + (g & 1) * 8 + lr) * ROWB
                                                + (kb + (g >> 1) * 8) * 2);
                ldsm_x4(a[mi][0], a[mi][1], a[mi][2], a[mi][3], addr);
            }
            uint32_t bfr[4][2];
            #pragma unroll
            for (int p = 0; p < 2; p++) {
                uint32_t r0, r1, r2, r3;
                uint32_t addr = sB + (uint32_t)((warp_n * 32 + p * 16 + (g >> 1) * 8 + lr) * ROWB
                                                + (kb + (g & 1) * 8) * 2);
                ldsm_x4(r0, r1, r2, r3, addr);
                bfr[p * 2 + 0][0] = r0; bfr[p * 2 + 0][1] = r1;
                bfr[p * 2 + 1][0] = r2; bfr[p * 2 + 1][1] = r3;
            }
            #pragma unroll
            for (int mi = 0; mi < 4; mi++)
                #pragma unroll
                for (int ni = 0; ni < 4; ni++)
                    mma_bf16(acc[mi][ni], a[mi], bfr[ni]);
        }
        // trailing __syncthreads removed: top-of-loop barrier already orders
        // buffer reuse for NSTG=3 (issue at s+1 targets buf written only after
        // all threads passed that barrier, i.e. finished mma of iter s)
    }

    const float sc = 1.0f / ((float)CD * TEMPER);
    const int qrow = lane >> 2;
    const int qcol = (lane & 3) * 2;

    float rowsum[4][2];
    float colsum[4][2];
    #pragma unroll
    for (int i = 0; i < 4; i++) { rowsum[i][0] = rowsum[i][1] = 0.f; colsum[i][0] = colsum[i][1] = 0.f; }

    #pragma unroll
    for (int mi = 0; mi < 4; mi++) {
        #pragma unroll
        for (int half = 0; half < 2; half++) {
            int lrow = warp_m * 64 + mi * 16 + half * 8 + qrow;
            bool rv = lrow < mrem;
            __half* dst = g_e + ((size_t)(b * LD) + m0 + lrow) * SD + n0;
            #pragma unroll
            for (int ni = 0; ni < 4; ni++) {
                int lcol = warp_n * 32 + ni * 8 + qcol;
                bool cv = lcol < nrem;
                float vx = acc[mi][ni][half * 2 + 0] * sc;
                float vy = acc[mi][ni][half * 2 + 1] * sc;
                float ex = (rv && cv) ? __expf(vx) : 0.f;
                float ey = (rv && cv) ? __expf(vy) : 0.f;
                if (rv && cv) {
                    __half2 h = __floats2half2_rn(ex * ex, ey * ey);  // exp(2*sim)
                    *reinterpret_cast<__half2*>(dst + lcol) = h;
                }
                rowsum[mi][half] += ex + ey;
                colsum[ni][0] += ex;
                colsum[ni][1] += ey;
            }
        }
    }
    #pragma unroll
    for (int mi = 0; mi < 4; mi++) {
        #pragma unroll
        for (int half = 0; half < 2; half++) {
            float r = rowsum[mi][half];
            r += __shfl_xor_sync(0xffffffffu, r, 1);
            r += __shfl_xor_sync(0xffffffffu, r, 2);
            if ((lane & 3) == 0) {
                int lrow = warp_m * 64 + mi * 16 + half * 8 + qrow;
                if (lrow < mrem) atomicAdd(&g_rsum[b * LD + m0 + lrow], r);
            }
        }
    }
    #pragma unroll
    for (int ni = 0; ni < 4; ni++) {
        #pragma unroll
        for (int c = 0; c < 2; c++) {
            float v = colsum[ni][c];
            v += __shfl_xor_sync(0xffffffffu, v, 4);
            v += __shfl_xor_sync(0xffffffffu, v, 8);
            v += __shfl_xor_sync(0xffffffffu, v, 16);
            if (lane < 4) {
                int lcol = warp_n * 32 + ni * 8 + qcol + c;
                if (lcol < nrem) atomicAdd(&g_csum[b * SD + n0 + lcol], v);
            }
        }
    }
}

// conf = e * inv_rs * inv_cs; one batch per launch (rowbase = b*LD)
#define CROWS 16
#define NV4 (SD / 4)              // 1200 slots of 4 elements
#define CTHR 512
__global__ void __launch_bounds__(CTHR, 3) k_conf(float* __restrict__ conf, int rowbase) {
    __shared__ float4 s_cinv[NV4];    // 19.2 KB
    const int r0 = rowbase + blockIdx.x * CROWS;
    const int n = rowbase / LD;
    const int tid = threadIdx.x;

    for (int i = tid; i < NV4; i += CTHR) {
        float4 cs = *reinterpret_cast<const float4*>(&g_csum[n * SD + i * 4]);
        float4 ci;
        ci.x = 1.f / cs.x; ci.y = 1.f / cs.y; ci.z = 1.f / cs.z; ci.w = 1.f / cs.w;
        s_cinv[i] = ci;
    }
    __syncthreads();

    float4 cmax[3];
    #pragma unroll
    for (int w = 0; w < 3; w++) cmax[w] = make_float4(0.f, 0.f, 0.f, 0.f);

    for (int rr = 0; rr < CROWS; rr += 2) {
        const int row0 = r0 + rr;
        const int row1 = row0 + 1;
        const float ir0 = 1.f / g_rsum[row0];
        const float ir1 = 1.f / g_rsum[row1];
        const __half2* ev0 = reinterpret_cast<const __half2*>(g_e + (size_t)row0 * SD);
        const __half2* ev1 = reinterpret_cast<const __half2*>(g_e + (size_t)row1 * SD);
        float4* cv0 = reinterpret_cast<float4*>(conf + (size_t)row0 * SD);
        float4* cv1 = reinterpret_cast<float4*>(conf + (size_t)row1 * SD);
        float bv0 = 0.f, bv1 = 0.f;
        int bi0 = 0, bi1 = 0;
        #pragma unroll
        for (int w = 0; w < 3; w++) {
            int i = tid + w * CTHR;
            if (i < NV4) {
                uint2 p0 = __ldcs(reinterpret_cast<const uint2*>(ev0 + 2 * i));
                uint2 p1 = __ldcs(reinterpret_cast<const uint2*>(ev1 + 2 * i));
                __half2 h00 = *reinterpret_cast<__half2*>(&p0.x);
                __half2 h01 = *reinterpret_cast<__half2*>(&p0.y);
                __half2 h10 = *reinterpret_cast<__half2*>(&p1.x);
                __half2 h11 = *reinterpret_cast<__half2*>(&p1.y);
                float2 e0a = __half22float2(h00), e0b = __half22float2(h01);
                float2 e1a = __half22float2(h10), e1b = __half22float2(h11);
                float4 ci = s_cinv[i];
                float4 c0, c1;
                c0.x = e0a.x * ci.x * ir0; c0.y = e0a.y * ci.y * ir0;
                c0.z = e0b.x * ci.z * ir0; c0.w = e0b.y * ci.w * ir0;
                c1.x = e1a.x * ci.x * ir1; c1.y = e1a.y * ci.y * ir1;
                c1.z = e1b.x * ci.z * ir1; c1.w = e1b.y * ci.w * ir1;
                __stcs(cv0 + i, c0);
                __stcs(cv1 + i, c1);
                int col = i * 4;
                if (c0.x > bv0) { bv0 = c0.x; bi0 = col; }
                if (c0.y > bv0) { bv0 = c0.y; bi0 = col + 1; }
                if (c0.z > bv0) { bv0 = c0.z; bi0 = col + 2; }
                if (c0.w > bv0) { bv0 = c0.w; bi0 = col + 3; }
                if (c1.x > bv1) { bv1 = c1.x; bi1 = col; }
                if (c1.y > bv1) { bv1 = c1.y; bi1 = col + 1; }
                if (c1.z > bv1) { bv1 = c1.z; bi1 = col + 2; }
                if (c1.w > bv1) { bv1 = c1.w; bi1 = col + 3; }
                cmax[w].x = fmaxf(cmax[w].x, fmaxf(c0.x, c1.x));
                cmax[w].y = fmaxf(cmax[w].y, fmaxf(c0.y, c1.y));
                cmax[w].z = fmaxf(cmax[w].z, fmaxf(c0.z, c1.z));
                cmax[w].w = fmaxf(cmax[w].w, fmaxf(c0.w, c1.w));
            }
        }
        #pragma unroll
        for (int o = 16; o; o >>= 1) {
            float ov0 = __shfl_xor_sync(0xffffffffu, bv0, o);
            int   oi0 = __shfl_xor_sync(0xffffffffu, bi0, o);
            if (ov0 > bv0 || (ov0 == bv0 && oi0 < bi0)) { bv0 = ov0; bi0 = oi0; }
            float ov1 = __shfl_xor_sync(0xffffffffu, bv1, o);
            int   oi1 = __shfl_xor_sync(0xffffffffu, bi1, o);
            if (ov1 > bv1 || (ov1 == bv1 && oi1 < bi1)) { bv1 = ov1; bi1 = oi1; }
        }
        if ((tid & 31) == 0) {
            unsigned long long k0 =
                ((unsigned long long)(uint32_t)__float_as_int(bv0) << 32) |
                (uint32_t)(0x7fffffff - bi0);
            unsigned long long k1 =
                ((unsigned long long)(uint32_t)__float_as_int(bv1) << 32) |
                (uint32_t)(0x7fffffff - bi1);
            atomicMax(&g_rkey[row0], k0);
            atomicMax(&g_rkey[row1], k1);
        }
    }
    #pragma unroll
    for (int w = 0; w < 3; w++) {
        int i = tid + w * CTHR;
        if (i < NV4) {
            int base = n * SD + i * 4;
            atomicMax(&g_ccmax[base + 0], __float_as_int(cmax[w].x));
            atomicMax(&g_ccmax[base + 1], __float_as_int(cmax[w].y));
            atomicMax(&g_ccmax[base + 2], __float_as_int(cmax[w].z));
            atomicMax(&g_ccmax[base + 3], __float_as_int(cmax[w].w));
        }
    }
}

// O(1) per-row match extraction from packed argmax keys
__global__ void __launch_bounds__(256) k_match(float* __restrict__ mmask,
                                               float* __restrict__ jids,
                                               float* __restrict__ mconf,
                                               const int* __restrict__ w0p,
                                               const int* __restrict__ w1p) {
    const int row = blockIdx.x * blockDim.x + threadIdx.x;
    if (row >= NB * LD) return;
    const int n = row / LD;
    const int l = row % LD;
    const int w0c = *w0p;
    const int w1c = *w1p;

    unsigned long long key = g_rkey[row];
    uint32_t vbits = (uint32_t)(key >> 32);
    int j = 0x7fffffff - (int)(key & 0xffffffffu);
    float v = __int_as_float((int)vbits);

    bool match = ((l / w0c) >= BORDER) && ((l % w0c) >= BORDER) &&
                 (v > THRESH) &&
                 ((j / w1c) >= BORDER) && ((j % w1c) >= BORDER) &&
                 ((int)vbits == g_ccmax[n * SD + j]);
    mmask[row] = match ? 1.f : 0.f;
    jids[row]  = (float)(match ? j : 0);
    mconf[row] = match ? v : 0.f;
}

// ---------------- launch ----------------
extern "C" void kernel_launch(void* const* d_in, const int* in_sizes, int n_in,
                              void* d_out, int out_size) {
    const float* f0 = (const float*)d_in[0];
    const float* f1 = (const float*)d_in[1];
    const int* w0 = (const int*)d_in[3];
    const int* w1 = (const int*)d_in[5];

    float* out = (float*)d_out;
    float* conf = out;
    const size_t NLS = (size_t)NB * LD * SD;
    float* mm = out + NLS;
    float* jj = mm + NB * LD;
    float* mc = jj + NB * LD;

    static int cfg_done = 0;
    static cudaStream_t s_side;
    static cudaEvent_t ev_g0, ev_g1, ev_join;
    if (!cfg_done) {
        cudaFuncSetAttribute(k_gemm_mma, cudaFuncAttributeMaxDynamicSharedMemorySize, DSMEM_B);
        cudaStreamCreateWithFlags(&s_side, cudaStreamNonBlocking);
        cudaEventCreateWithFlags(&ev_g0, cudaEventDisableTiming);
        cudaEventCreateWithFlags(&ev_g1, cudaEventDisableTiming);
        cudaEventCreateWithFlags(&ev_join, cudaEventDisableTiming);
        cfg_done = 1;
    }

    dim3 gg((SD + TN - 1) / TN, (LD + TM - 1) / TM, 1);

    // main stream: init, convert, gemm(b0)
    k_init<<<(NB * SD + 255) / 256, 256>>>();
    k_convert<<<(NB * LD * (CD / 4) + 255) / 256, 256>>>(f0, f1);
    k_gemm_mma<<<gg, 256, DSMEM_B>>>(0);
    cudaEventRecord(ev_g0, 0);

    // side stream: conf(b0) overlapped with gemm(b1) on main
    cudaStreamWaitEvent(s_side, ev_g0, 0);
    k_conf<<<LD / CROWS, CTHR, 0, s_side>>>(conf, 0);

    k_gemm_mma<<<gg, 256, DSMEM_B>>>(1);
    cudaEventRecord(ev_g1, 0);

    cudaStreamWaitEvent(s_side, ev_g1, 0);
    k_conf<<<LD / CROWS, CTHR, 0, s_side>>>(conf, LD);
    cudaEventRecord(ev_join, s_side);

    // join back to main stream, then match
    cudaStreamWaitEvent(0, ev_join, 0);
    k_match<<<(NB * LD + 255) / 256, 256>>>(mm, jj, mc, w0, w1);
}

// round 15
// speedup vs baseline: 1.0774x; 1.0774x over previous
#include <cuda_runtime.h>
#include <cuda_bf16.h>
#include <cuda_fp16.h>
#include <cstdint>

#define NB 2
#define LD 4800
#define SD 4800
#define CD 256
#define TEMPER 0.1f
#define THRESH 0.2f
#define BORDER 2

#define KTOT 768          // A_cat=[hi|hi|lo], B_cat=[hi|lo|hi]
#define TM 128
#define TN 128
#define KC 64
#define NCHUNK (KTOT / KC)
#define ROWB 144
#define ABUF_B (TM * ROWB)
#define BBUF_B (TN * ROWB)
#define STG_B (ABUF_B + BBUF_B)
#define NSTG 3
#define DSMEM_B (NSTG * STG_B)

// ---------------- scratch ----------------
__device__ __half g_e[(size_t)NB * LD * SD];      // exp(2*sim) in fp16 (92 MB)
__device__ __align__(128) __nv_bfloat16 g_acat[(size_t)NB * LD * KTOT];
__device__ __align__(128) __nv_bfloat16 g_bcat[(size_t)NB * SD * KTOT];
__device__ float g_rsum[NB * LD];
__device__ float g_csum[NB * SD];
__device__ unsigned long long g_rkey[NB * LD];   // (conf_rowmax_bits<<32)|(0x7fffffff-idx)
__device__ int g_ccmax[NB * SD];                  // conf col max bits

// ---------------- PTX helpers ----------------
__device__ __forceinline__ uint32_t s2u(const void* p) {
    uint32_t a;
    asm("{ .reg .u64 t; cvta.to.shared.u64 t, %1; cvt.u32.u64 %0, t; }" : "=r"(a) : "l"(p));
    return a;
}
__device__ __forceinline__ void ldsm_x4(uint32_t& r0, uint32_t& r1, uint32_t& r2, uint32_t& r3,
                                        uint32_t addr) {
    asm volatile("ldmatrix.sync.aligned.m8n8.x4.shared.b16 {%0,%1,%2,%3}, [%4];"
                 : "=r"(r0), "=r"(r1), "=r"(r2), "=r"(r3) : "r"(addr));
}
__device__ __forceinline__ void mma_bf16(float* d, const uint32_t* a, const uint32_t* b) {
    asm volatile(
        "mma.sync.aligned.m16n8k16.row.col.f32.bf16.bf16.f32 "
        "{%0,%1,%2,%3}, {%4,%5,%6,%7}, {%8,%9}, {%0,%1,%2,%3};"
        : "+f"(d[0]), "+f"(d[1]), "+f"(d[2]), "+f"(d[3])
        : "r"(a[0]), "r"(a[1]), "r"(a[2]), "r"(a[3]), "r"(b[0]), "r"(b[1]));
}
__device__ __forceinline__ void cp16(uint32_t dst, const void* src, bool pred) {
    int sz = pred ? 16 : 0;
    asm volatile("cp.async.cg.shared.global [%0], [%1], 16, %2;"
                 :: "r"(dst), "l"(src), "r"(sz) : "memory");
}
#define CP_COMMIT() asm volatile("cp.async.commit_group;" ::: "memory")
#define CP_WAIT1()  asm volatile("cp.async.wait_group 1;" ::: "memory")
#define CP_WAIT0()  asm volatile("cp.async.wait_group 0;" ::: "memory")

// fp32x4 -> packed bf16 hi/lo pairs
__device__ __forceinline__ void split4(const float4& x, uint2& hp, uint2& lp) {
    __nv_bfloat16 h0 = __float2bfloat16(x.x), h1 = __float2bfloat16(x.y);
    __nv_bfloat16 h2 = __float2bfloat16(x.z), h3 = __float2bfloat16(x.w);
    __nv_bfloat16 l0 = __float2bfloat16(x.x - __bfloat162float(h0));
    __nv_bfloat16 l1 = __float2bfloat16(x.y - __bfloat162float(h1));
    __nv_bfloat16 l2 = __float2bfloat16(x.z - __bfloat162float(h2));
    __nv_bfloat16 l3 = __float2bfloat16(x.w - __bfloat162float(h3));
    __nv_bfloat162 a01 = __nv_bfloat162(h0, h1), a23 = __nv_bfloat162(h2, h3);
    __nv_bfloat162 b01 = __nv_bfloat162(l0, l1), b23 = __nv_bfloat162(l2, l3);
    hp.x = *reinterpret_cast<uint32_t*>(&a01); hp.y = *reinterpret_cast<uint32_t*>(&a23);
    lp.x = *reinterpret_cast<uint32_t*>(&b01); lp.y = *reinterpret_cast<uint32_t*>(&b23);
}

// ---------------- kernels ----------------
// convert + fused stats-init (disjoint writes, no ordering hazard)
__global__ void __launch_bounds__(256) k_convert(const float* __restrict__ f0,
                                                 const float* __restrict__ f1) {
    int idx = blockIdx.x * blockDim.x + threadIdx.x;
    if (idx < NB * SD) {
        g_rsum[idx] = 0.f;
        g_csum[idx] = 0.f;
        g_rkey[idx] = 0ull;
        g_ccmax[idx] = 0;
    }
    if (idx >= NB * LD * (CD / 4)) return;
    int row = idx / (CD / 4);
    int c = (idx % (CD / 4)) * 4;
    {
        float4 x = *reinterpret_cast<const float4*>(f0 + (size_t)row * CD + c);
        uint2 hp, lp; split4(x, hp, lp);
        __nv_bfloat16* r = g_acat + (size_t)row * KTOT;
        *reinterpret_cast<uint2*>(r + c) = hp;
        *reinterpret_cast<uint2*>(r + CD + c) = hp;
        *reinterpret_cast<uint2*>(r + 2 * CD + c) = lp;
    }
    {
        float4 x = *reinterpret_cast<const float4*>(f1 + (size_t)row * CD + c);
        uint2 hp, lp; split4(x, hp, lp);
        __nv_bfloat16* r = g_bcat + (size_t)row * KTOT;
        *reinterpret_cast<uint2*>(r + c) = hp;
        *reinterpret_cast<uint2*>(r + CD + c) = lp;
        *reinterpret_cast<uint2*>(r + 2 * CD + c) = hp;
    }
}

// HMMA bf16 GEMM 128x128 -> fp16 exp(2*sim) + fused stats
__global__ void __launch_bounds__(256, 2) k_gemm_mma() {
    extern __shared__ char smem[];
    const int tid = threadIdx.x;
    const int wid = tid >> 5;
    const int lane = tid & 31;
    const int warp_m = wid & 1;
    const int warp_n = wid >> 1;

    const int b  = blockIdx.z;
    const int m0 = blockIdx.y * TM;
    const int n0 = blockIdx.x * TN;
    const int mrem = min(TM, LD - m0);
    const int nrem = min(TN, SD - n0);

    const __nv_bfloat16* Abase = g_acat + (size_t)(b * LD + m0) * KTOT;
    const __nv_bfloat16* Bbase = g_bcat + (size_t)(b * SD + n0) * KTOT;
    const uint32_t sbase = s2u(smem);

    float acc[4][4][4];
    #pragma unroll
    for (int i = 0; i < 4; i++)
        #pragma unroll
        for (int j = 0; j < 4; j++)
            #pragma unroll
            for (int q = 0; q < 4; q++) acc[i][j][q] = 0.f;

    auto issue = [&](int chunk, int buf) {
        const int k0 = chunk * KC;
        const uint32_t sA = sbase + buf * STG_B;
        const uint32_t sB = sA + ABUF_B;
        #pragma unroll
        for (int i = 0; i < 4; i++) {
            int f = tid + i * 256;
            int row = f >> 3, q = f & 7;
            bool pa = row < mrem;
            int ra = pa ? row : 0;
            cp16(sA + row * ROWB + q * 16, Abase + (size_t)ra * KTOT + k0 + q * 8, pa);
            bool pb = row < nrem;
            int rb = pb ? row : 0;
            cp16(sB + row * ROWB + q * 16, Bbase + (size_t)rb * KTOT + k0 + q * 8, pb);
        }
        CP_COMMIT();
    };

    issue(0, 0);
    issue(1, 1);

    const int g = lane >> 3;
    const int lr = lane & 7;

    for (int s = 0; s < NCHUNK; s++) {
        if (s == NCHUNK - 1) { CP_WAIT0(); } else { CP_WAIT1(); }
        __syncthreads();
        const int buf = s % NSTG;
        const uint32_t sA = sbase + buf * STG_B;
        const uint32_t sB = sA + ABUF_B;
        if (s + 2 < NCHUNK) issue(s + 2, (s + 2) % NSTG);

        #pragma unroll
        for (int ks = 0; ks < KC / 16; ks++) {
            const int kb = ks * 16;
            uint32_t a[4][4];
            #pragma unroll
            for (int mi = 0; mi < 4; mi++) {
                uint32_t addr = sA + (uint32_t)((warp_m * 64 + mi * 16 + (g & 1) * 8 + lr) * ROWB
                                                + (kb + (g >> 1) * 8) * 2);
                ldsm_x4(a[mi][0], a[mi][1], a[mi][2], a[mi][3], addr);
            }
            uint32_t bfr[4][2];
            #pragma unroll
            for (int p = 0; p < 2; p++) {
                uint32_t r0, r1, r2, r3;
                uint32_t addr = sB + (uint32_t)((warp_n * 32 + p * 16 + (g >> 1) * 8 + lr) * ROWB
                                                + (kb + (g & 1) * 8) * 2);
                ldsm_x4(r0, r1, r2, r3, addr);
                bfr[p * 2 + 0][0] = r0; bfr[p * 2 + 0][1] = r1;
                bfr[p * 2 + 1][0] = r2; bfr[p * 2 + 1][1] = r3;
            }
            #pragma unroll
            for (int mi = 0; mi < 4; mi++)
                #pragma unroll
                for (int ni = 0; ni < 4; ni++)
                    mma_bf16(acc[mi][ni], a[mi], bfr[ni]);
        }
        // trailing __syncthreads removed: top-of-loop barrier already orders
        // buffer reuse for NSTG=3 (verified correct in round 14)
    }

    const float sc = 1.0f / ((float)CD * TEMPER);
    const int qrow = lane >> 2;
    const int qcol = (lane & 3) * 2;

    float rowsum[4][2];
    float colsum[4][2];
    #pragma unroll
    for (int i = 0; i < 4; i++) { rowsum[i][0] = rowsum[i][1] = 0.f; colsum[i][0] = colsum[i][1] = 0.f; }

    #pragma unroll
    for (int mi = 0; mi < 4; mi++) {
        #pragma unroll
        for (int half = 0; half < 2; half++) {
            int lrow = warp_m * 64 + mi * 16 + half * 8 + qrow;
            bool rv = lrow < mrem;
            __half* dst = g_e + ((size_t)(b * LD) + m0 + lrow) * SD + n0;
            #pragma unroll
            for (int ni = 0; ni < 4; ni++) {
                int lcol = warp_n * 32 + ni * 8 + qcol;
                bool cv = lcol < nrem;
                float vx = acc[mi][ni][half * 2 + 0] * sc;
                float vy = acc[mi][ni][half * 2 + 1] * sc;
                float ex = (rv && cv) ? __expf(vx) : 0.f;
                float ey = (rv && cv) ? __expf(vy) : 0.f;
                if (rv && cv) {
                    __half2 h = __floats2half2_rn(ex * ex, ey * ey);  // exp(2*sim)
                    *reinterpret_cast<__half2*>(dst + lcol) = h;
                }
                rowsum[mi][half] += ex + ey;
                colsum[ni][0] += ex;
                colsum[ni][1] += ey;
            }
        }
    }
    #pragma unroll
    for (int mi = 0; mi < 4; mi++) {
        #pragma unroll
        for (int half = 0; half < 2; half++) {
            float r = rowsum[mi][half];
            r += __shfl_xor_sync(0xffffffffu, r, 1);
            r += __shfl_xor_sync(0xffffffffu, r, 2);
            if ((lane & 3) == 0) {
                int lrow = warp_m * 64 + mi * 16 + half * 8 + qrow;
                if (lrow < mrem) atomicAdd(&g_rsum[b * LD + m0 + lrow], r);
            }
        }
    }
    #pragma unroll
    for (int ni = 0; ni < 4; ni++) {
        #pragma unroll
        for (int c = 0; c < 2; c++) {
            float v = colsum[ni][c];
            v += __shfl_xor_sync(0xffffffffu, v, 4);
            v += __shfl_xor_sync(0xffffffffu, v, 8);
            v += __shfl_xor_sync(0xffffffffu, v, 16);
            if (lane < 4) {
                int lcol = warp_n * 32 + ni * 8 + qcol + c;
                if (lcol < nrem) atomicAdd(&g_csum[b * SD + n0 + lcol], v);
            }
        }
    }
}

// conf = e * inv_rs * inv_cs; fp16 e reads; row argmax key + col maxes
#define CROWS 16
#define NV4 (SD / 4)              // 1200 slots of 4 elements
#define CTHR 512
__global__ void __launch_bounds__(CTHR, 3) k_conf(float* __restrict__ conf) {
    __shared__ float4 s_cinv[NV4];    // 19.2 KB
    const int r0 = blockIdx.x * CROWS;
    const int n = r0 / LD;
    const int tid = threadIdx.x;

    for (int i = tid; i < NV4; i += CTHR) {
        float4 cs = *reinterpret_cast<const float4*>(&g_csum[n * SD + i * 4]);
        float4 ci;
        ci.x = 1.f / cs.x; ci.y = 1.f / cs.y; ci.z = 1.f / cs.z; ci.w = 1.f / cs.w;
        s_cinv[i] = ci;
    }
    __syncthreads();

    float4 cmax[3];
    #pragma unroll
    for (int w = 0; w < 3; w++) cmax[w] = make_float4(0.f, 0.f, 0.f, 0.f);

    for (int rr = 0; rr < CROWS; rr += 2) {
        const int row0 = r0 + rr;
        const int row1 = row0 + 1;
        const float ir0 = 1.f / g_rsum[row0];
        const float ir1 = 1.f / g_rsum[row1];
        const __half2* ev0 = reinterpret_cast<const __half2*>(g_e + (size_t)row0 * SD);
        const __half2* ev1 = reinterpret_cast<const __half2*>(g_e + (size_t)row1 * SD);
        float4* cv0 = reinterpret_cast<float4*>(conf + (size_t)row0 * SD);
        float4* cv1 = reinterpret_cast<float4*>(conf + (size_t)row1 * SD);
        float bv0 = 0.f, bv1 = 0.f;
        int bi0 = 0, bi1 = 0;
        #pragma unroll
        for (int w = 0; w < 3; w++) {
            int i = tid + w * CTHR;
            if (i < NV4) {
                uint2 p0 = __ldcs(reinterpret_cast<const uint2*>(ev0 + 2 * i));
                uint2 p1 = __ldcs(reinterpret_cast<const uint2*>(ev1 + 2 * i));
                __half2 h00 = *reinterpret_cast<__half2*>(&p0.x);
                __half2 h01 = *reinterpret_cast<__half2*>(&p0.y);
                __half2 h10 = *reinterpret_cast<__half2*>(&p1.x);
                __half2 h11 = *reinterpret_cast<__half2*>(&p1.y);
                float2 e0a = __half22float2(h00), e0b = __half22float2(h01);
                float2 e1a = __half22float2(h10), e1b = __half22float2(h11);
                float4 ci = s_cinv[i];
                float4 c0, c1;
                c0.x = e0a.x * ci.x * ir0; c0.y = e0a.y * ci.y * ir0;
                c0.z = e0b.x * ci.z * ir0; c0.w = e0b.y * ci.w * ir0;
                c1.x = e1a.x * ci.x * ir1; c1.y = e1a.y * ci.y * ir1;
                c1.z = e1b.x * ci.z * ir1; c1.w = e1b.y * ci.w * ir1;
                __stcs(cv0 + i, c0);
                __stcs(cv1 + i, c1);
                int col = i * 4;
                if (c0.x > bv0) { bv0 = c0.x; bi0 = col; }
                if (c0.y > bv0) { bv0 = c0.y; bi0 = col + 1; }
                if (c0.z > bv0) { bv0 = c0.z; bi0 = col + 2; }
                if (c0.w > bv0) { bv0 = c0.w; bi0 = col + 3; }
                if (c1.x > bv1) { bv1 = c1.x; bi1 = col; }
                if (c1.y > bv1) { bv1 = c1.y; bi1 = col + 1; }
                if (c1.z > bv1) { bv1 = c1.z; bi1 = col + 2; }
                if (c1.w > bv1) { bv1 = c1.w; bi1 = col + 3; }
                cmax[w].x = fmaxf(cmax[w].x, fmaxf(c0.x, c1.x));
                cmax[w].y = fmaxf(cmax[w].y, fmaxf(c0.y, c1.y));
                cmax[w].z = fmaxf(cmax[w].z, fmaxf(c0.z, c1.z));
                cmax[w].w = fmaxf(cmax[w].w, fmaxf(c0.w, c1.w));
            }
        }
        #pragma unroll
        for (int o = 16; o; o >>= 1) {
            float ov0 = __shfl_xor_sync(0xffffffffu, bv0, o);
            int   oi0 = __shfl_xor_sync(0xffffffffu, bi0, o);
            if (ov0 > bv0 || (ov0 == bv0 && oi0 < bi0)) { bv0 = ov0; bi0 = oi0; }
            float ov1 = __shfl_xor_sync(0xffffffffu, bv1, o);
            int   oi1 = __shfl_xor_sync(0xffffffffu, bi1, o);
            if (ov1 > bv1 || (ov1 == bv1 && oi1 < bi1)) { bv1 = ov1; bi1 = oi1; }
        }
        if ((tid & 31) == 0) {
            unsigned long long k0 =
                ((unsigned long long)(uint32_t)__float_as_int(bv0) << 32) |
                (uint32_t)(0x7fffffff - bi0);
            unsigned long long k1 =
                ((unsigned long long)(uint32_t)__float_as_int(bv1) << 32) |
                (uint32_t)(0x7fffffff - bi1);
            atomicMax(&g_rkey[row0], k0);
            atomicMax(&g_rkey[row1], k1);
        }
    }
    #pragma unroll
    for (int w = 0; w < 3; w++) {
        int i = tid + w * CTHR;
        if (i < NV4) {
            int base = n * SD + i * 4;
            atomicMax(&g_ccmax[base + 0], __float_as_int(cmax[w].x));
            atomicMax(&g_ccmax[base + 1], __float_as_int(cmax[w].y));
            atomicMax(&g_ccmax[base + 2], __float_as_int(cmax[w].z));
            atomicMax(&g_ccmax[base + 3], __float_as_int(cmax[w].w));
        }
    }
}

// O(1) per-row match extraction from packed argmax keys
__global__ void __launch_bounds__(256) k_match(float* __restrict__ mmask,
                                               float* __restrict__ jids,
                                               float* __restrict__ mconf,
                                               const int* __restrict__ w0p,
                                               const int* __restrict__ w1p) {
    const int row = blockIdx.x * blockDim.x + threadIdx.x;
    if (row >= NB * LD) return;
    const int n = row / LD;
    const int l = row % LD;
    const int w0c = *w0p;
    const int w1c = *w1p;

    unsigned long long key = g_rkey[row];
    uint32_t vbits = (uint32_t)(key >> 32);
    int j = 0x7fffffff - (int)(key & 0xffffffffu);
    float v = __int_as_float((int)vbits);

    bool match = ((l / w0c) >= BORDER) && ((l % w0c) >= BORDER) &&
                 (v > THRESH) &&
                 ((j / w1c) >= BORDER) && ((j % w1c) >= BORDER) &&
                 ((int)vbits == g_ccmax[n * SD + j]);
    mmask[row] = match ? 1.f : 0.f;
    jids[row]  = (float)(match ? j : 0);
    mconf[row] = match ? v : 0.f;
}

// ---------------- launch ----------------
extern "C" void kernel_launch(void* const* d_in, const int* in_sizes, int n_in,
                              void* d_out, int out_size) {
    const float* f0 = (const float*)d_in[0];
    const float* f1 = (const float*)d_in[1];
    const int* w0 = (const int*)d_in[3];
    const int* w1 = (const int*)d_in[5];

    float* out = (float*)d_out;
    float* conf = out;
    const size_t NLS = (size_t)NB * LD * SD;
    float* mm = out + NLS;
    float* jj = mm + NB * LD;
    float* mc = jj + NB * LD;

    static int cfg_done = 0;
    if (!cfg_done) {
        cudaFuncSetAttribute(k_gemm_mma, cudaFuncAttributeMaxDynamicSharedMemorySize, DSMEM_B);
        cfg_done = 1;
    }

    k_convert<<<(NB * LD * (CD / 4) + 255) / 256, 256>>>(f0, f1);
    dim3 gg((SD + TN - 1) / TN, (LD + TM - 1) / TM, NB);
    k_gemm_mma<<<gg, 256, DSMEM_B>>>();
    k_conf<<<NB * LD / CROWS, CTHR>>>(conf);
    k_match<<<(NB * LD + 255) / 256, 256>>>(mm, jj, mc, w0, w1);
}

// round 16
// speedup vs baseline: 1.0949x; 1.0162x over previous
#include <cuda_runtime.h>
#include <cuda_bf16.h>
#include <cuda_fp16.h>
#include <cstdint>

#define NB 2
#define LD 4800
#define SD 4800
#define CD 256
#define TEMPER 0.1f
#define THRESH 0.2f
#define BORDER 2

#define KTOT 768          // A_cat=[hi|hi|lo], B_cat=[hi|lo|hi]
#define TM 128
#define TN 128
#define KC 64
#define NCHUNK (KTOT / KC)
#define ROWB 144
#define ABUF_B (TM * ROWB)
#define BBUF_B (TN * ROWB)
#define STG_B (ABUF_B + BBUF_B)
#define NSTG 3
#define DSMEM_B (NSTG * STG_B)

// ---------------- scratch ----------------
__device__ __half g_e[(size_t)NB * LD * SD];      // exp(2*sim) in fp16 (92 MB)
__device__ __align__(128) __nv_bfloat16 g_acat[(size_t)NB * LD * KTOT];
__device__ __align__(128) __nv_bfloat16 g_bcat[(size_t)NB * SD * KTOT];
__device__ float g_rsum[NB * LD];
__device__ float g_csum[NB * SD];
__device__ int g_rcmax[NB * LD];                  // conf row max bits
__device__ int g_ccmax[NB * SD];                  // conf col max bits

// ---------------- PTX helpers ----------------
__device__ __forceinline__ uint32_t s2u(const void* p) {
    uint32_t a;
    asm("{ .reg .u64 t; cvta.to.shared.u64 t, %1; cvt.u32.u64 %0, t; }" : "=r"(a) : "l"(p));
    return a;
}
__device__ __forceinline__ void ldsm_x4(uint32_t& r0, uint32_t& r1, uint32_t& r2, uint32_t& r3,
                                        uint32_t addr) {
    asm volatile("ldmatrix.sync.aligned.m8n8.x4.shared.b16 {%0,%1,%2,%3}, [%4];"
                 : "=r"(r0), "=r"(r1), "=r"(r2), "=r"(r3) : "r"(addr));
}
__device__ __forceinline__ void mma_bf16(float* d, const uint32_t* a, const uint32_t* b) {
    asm volatile(
        "mma.sync.aligned.m16n8k16.row.col.f32.bf16.bf16.f32 "
        "{%0,%1,%2,%3}, {%4,%5,%6,%7}, {%8,%9}, {%0,%1,%2,%3};"
        : "+f"(d[0]), "+f"(d[1]), "+f"(d[2]), "+f"(d[3])
        : "r"(a[0]), "r"(a[1]), "r"(a[2]), "r"(a[3]), "r"(b[0]), "r"(b[1]));
}
__device__ __forceinline__ void cp16(uint32_t dst, const void* src, bool pred) {
    int sz = pred ? 16 : 0;
    asm volatile("cp.async.cg.shared.global [%0], [%1], 16, %2;"
                 :: "r"(dst), "l"(src), "r"(sz) : "memory");
}
#define CP_COMMIT() asm volatile("cp.async.commit_group;" ::: "memory")
#define CP_WAIT1()  asm volatile("cp.async.wait_group 1;" ::: "memory")
#define CP_WAIT0()  asm volatile("cp.async.wait_group 0;" ::: "memory")

__device__ __forceinline__ float warpMaxF(float v) {
    #pragma unroll
    for (int o = 16; o; o >>= 1) v = fmaxf(v, __shfl_xor_sync(0xffffffffu, v, o));
    return v;
}
__device__ __forceinline__ int warpMinI(int v) {
    #pragma unroll
    for (int o = 16; o; o >>= 1) v = min(v, __shfl_xor_sync(0xffffffffu, v, o));
    return v;
}

// fp32x4 -> packed bf16 hi/lo pairs
__device__ __forceinline__ void split4(const float4& x, uint2& hp, uint2& lp) {
    __nv_bfloat16 h0 = __float2bfloat16(x.x), h1 = __float2bfloat16(x.y);
    __nv_bfloat16 h2 = __float2bfloat16(x.z), h3 = __float2bfloat16(x.w);
    __nv_bfloat16 l0 = __float2bfloat16(x.x - __bfloat162float(h0));
    __nv_bfloat16 l1 = __float2bfloat16(x.y - __bfloat162float(h1));
    __nv_bfloat16 l2 = __float2bfloat16(x.z - __bfloat162float(h2));
    __nv_bfloat16 l3 = __float2bfloat16(x.w - __bfloat162float(h3));
    __nv_bfloat162 a01 = __nv_bfloat162(h0, h1), a23 = __nv_bfloat162(h2, h3);
    __nv_bfloat162 b01 = __nv_bfloat162(l0, l1), b23 = __nv_bfloat162(l2, l3);
    hp.x = *reinterpret_cast<uint32_t*>(&a01); hp.y = *reinterpret_cast<uint32_t*>(&a23);
    lp.x = *reinterpret_cast<uint32_t*>(&b01); lp.y = *reinterpret_cast<uint32_t*>(&b23);
}

// ---------------- kernels ----------------
// convert + fused stats-init (disjoint writes, no ordering hazard)
__global__ void __launch_bounds__(256) k_convert(const float* __restrict__ f0,
                                                 const float* __restrict__ f1) {
    int idx = blockIdx.x * blockDim.x + threadIdx.x;
    if (idx < NB * SD) {
        g_rsum[idx] = 0.f;
        g_csum[idx] = 0.f;
        g_rcmax[idx] = 0;
        g_ccmax[idx] = 0;
    }
    if (idx >= NB * LD * (CD / 4)) return;
    int row = idx / (CD / 4);
    int c = (idx % (CD / 4)) * 4;
    {
        float4 x = *reinterpret_cast<const float4*>(f0 + (size_t)row * CD + c);
        uint2 hp, lp; split4(x, hp, lp);
        __nv_bfloat16* r = g_acat + (size_t)row * KTOT;
        *reinterpret_cast<uint2*>(r + c) = hp;
        *reinterpret_cast<uint2*>(r + CD + c) = hp;
        *reinterpret_cast<uint2*>(r + 2 * CD + c) = lp;
    }
    {
        float4 x = *reinterpret_cast<const float4*>(f1 + (size_t)row * CD + c);
        uint2 hp, lp; split4(x, hp, lp);
        __nv_bfloat16* r = g_bcat + (size_t)row * KTOT;
        *reinterpret_cast<uint2*>(r + c) = hp;
        *reinterpret_cast<uint2*>(r + CD + c) = lp;
        *reinterpret_cast<uint2*>(r + 2 * CD + c) = hp;
    }
}

// HMMA bf16 GEMM 128x128 -> fp16 exp(2*sim) + fused stats
__global__ void __launch_bounds__(256, 2) k_gemm_mma() {
    extern __shared__ char smem[];
    const int tid = threadIdx.x;
    const int wid = tid >> 5;
    const int lane = tid & 31;
    const int warp_m = wid & 1;
    const int warp_n = wid >> 1;

    const int b  = blockIdx.z;
    const int m0 = blockIdx.y * TM;
    const int n0 = blockIdx.x * TN;
    const int mrem = min(TM, LD - m0);
    const int nrem = min(TN, SD - n0);

    const __nv_bfloat16* Abase = g_acat + (size_t)(b * LD + m0) * KTOT;
    const __nv_bfloat16* Bbase = g_bcat + (size_t)(b * SD + n0) * KTOT;
    const uint32_t sbase = s2u(smem);

    float acc[4][4][4];
    #pragma unroll
    for (int i = 0; i < 4; i++)
        #pragma unroll
        for (int j = 0; j < 4; j++)
            #pragma unroll
            for (int q = 0; q < 4; q++) acc[i][j][q] = 0.f;

    auto issue = [&](int chunk, int buf) {
        const int k0 = chunk * KC;
        const uint32_t sA = sbase + buf * STG_B;
        const uint32_t sB = sA + ABUF_B;
        #pragma unroll
        for (int i = 0; i < 4; i++) {
            int f = tid + i * 256;
            int row = f >> 3, q = f & 7;
            bool pa = row < mrem;
            int ra = pa ? row : 0;
            cp16(sA + row * ROWB + q * 16, Abase + (size_t)ra * KTOT + k0 + q * 8, pa);
            bool pb = row < nrem;
            int rb = pb ? row : 0;
            cp16(sB + row * ROWB + q * 16, Bbase + (size_t)rb * KTOT + k0 + q * 8, pb);
        }
        CP_COMMIT();
    };

    issue(0, 0);
    issue(1, 1);

    const int g = lane >> 3;
    const int lr = lane & 7;

    for (int s = 0; s < NCHUNK; s++) {
        if (s == NCHUNK - 1) { CP_WAIT0(); } else { CP_WAIT1(); }
        __syncthreads();
        const int buf = s % NSTG;
        const uint32_t sA = sbase + buf * STG_B;
        const uint32_t sB = sA + ABUF_B;
        if (s + 2 < NCHUNK) issue(s + 2, (s + 2) % NSTG);

        #pragma unroll
        for (int ks = 0; ks < KC / 16; ks++) {
            const int kb = ks * 16;
            uint32_t a[4][4];
            #pragma unroll
            for (int mi = 0; mi < 4; mi++) {
                uint32_t addr = sA + (uint32_t)((warp_m * 64 + mi * 16 + (g & 1) * 8 + lr) * ROWB
                                                + (kb + (g >> 1) * 8) * 2);
                ldsm_x4(a[mi][0], a[mi][1], a[mi][2], a[mi][3], addr);
            }
            uint32_t bfr[4][2];
            #pragma unroll
            for (int p = 0; p < 2; p++) {
                uint32_t r0, r1, r2, r3;
                uint32_t addr = sB + (uint32_t)((warp_n * 32 + p * 16 + (g >> 1) * 8 + lr) * ROWB
                                                + (kb + (g & 1) * 8) * 2);
                ldsm_x4(r0, r1, r2, r3, addr);
                bfr[p * 2 + 0][0] = r0; bfr[p * 2 + 0][1] = r1;
                bfr[p * 2 + 1][0] = r2; bfr[p * 2 + 1][1] = r3;
            }
            #pragma unroll
            for (int mi = 0; mi < 4; mi++)
                #pragma unroll
                for (int ni = 0; ni < 4; ni++)
                    mma_bf16(acc[mi][ni], a[mi], bfr[ni]);
        }
        // trailing __syncthreads removed (verified round 14)
    }

    const float sc = 1.0f / ((float)CD * TEMPER);
    const int qrow = lane >> 2;
    const int qcol = (lane & 3) * 2;

    float rowsum[4][2];
    float colsum[4][2];
    #pragma unroll
    for (int i = 0; i < 4; i++) { rowsum[i][0] = rowsum[i][1] = 0.f; colsum[i][0] = colsum[i][1] = 0.f; }

    #pragma unroll
    for (int mi = 0; mi < 4; mi++) {
        #pragma unroll
        for (int half = 0; half < 2; half++) {
            int lrow = warp_m * 64 + mi * 16 + half * 8 + qrow;
            bool rv = lrow < mrem;
            __half* dst = g_e + ((size_t)(b * LD) + m0 + lrow) * SD + n0;
            #pragma unroll
            for (int ni = 0; ni < 4; ni++) {
                int lcol = warp_n * 32 + ni * 8 + qcol;
                bool cv = lcol < nrem;
                float vx = acc[mi][ni][half * 2 + 0] * sc;
                float vy = acc[mi][ni][half * 2 + 1] * sc;
                float ex = (rv && cv) ? __expf(vx) : 0.f;
                float ey = (rv && cv) ? __expf(vy) : 0.f;
                if (rv && cv) {
                    __half2 h = __floats2half2_rn(ex * ex, ey * ey);  // exp(2*sim)
                    *reinterpret_cast<__half2*>(dst + lcol) = h;
                }
                rowsum[mi][half] += ex + ey;
                colsum[ni][0] += ex;
                colsum[ni][1] += ey;
            }
        }
    }
    #pragma unroll
    for (int mi = 0; mi < 4; mi++) {
        #pragma unroll
        for (int half = 0; half < 2; half++) {
            float r = rowsum[mi][half];
            r += __shfl_xor_sync(0xffffffffu, r, 1);
            r += __shfl_xor_sync(0xffffffffu, r, 2);
            if ((lane & 3) == 0) {
                int lrow = warp_m * 64 + mi * 16 + half * 8 + qrow;
                if (lrow < mrem) atomicAdd(&g_rsum[b * LD + m0 + lrow], r);
            }
        }
    }
    #pragma unroll
    for (int ni = 0; ni < 4; ni++) {
        #pragma unroll
        for (int c = 0; c < 2; c++) {
            float v = colsum[ni][c];
            v += __shfl_xor_sync(0xffffffffu, v, 4);
            v += __shfl_xor_sync(0xffffffffu, v, 8);
            v += __shfl_xor_sync(0xffffffffu, v, 16);
            if (lane < 4) {
                int lcol = warp_n * 32 + ni * 8 + qcol + c;
                if (lcol < nrem) atomicAdd(&g_csum[b * SD + n0 + lcol], v);
            }
        }
    }
}

// conf = e * inv_rs * inv_cs; pure fmax row/col maxes (no argmax tracking)
#define CROWS 16
#define NV4 (SD / 4)              // 1200 slots of 4 elements
#define CTHR 512
__global__ void __launch_bounds__(CTHR, 3) k_conf(float* __restrict__ conf) {
    __shared__ float4 s_cinv[NV4];    // 19.2 KB
    const int r0 = blockIdx.x * CROWS;
    const int n = r0 / LD;
    const int tid = threadIdx.x;

    for (int i = tid; i < NV4; i += CTHR) {
        float4 cs = *reinterpret_cast<const float4*>(&g_csum[n * SD + i * 4]);
        float4 ci;
        ci.x = 1.f / cs.x; ci.y = 1.f / cs.y; ci.z = 1.f / cs.z; ci.w = 1.f / cs.w;
        s_cinv[i] = ci;
    }
    __syncthreads();

    float4 cmax[3];
    #pragma unroll
    for (int w = 0; w < 3; w++) cmax[w] = make_float4(0.f, 0.f, 0.f, 0.f);

    for (int rr = 0; rr < CROWS; rr += 2) {
        const int row0 = r0 + rr;
        const int row1 = row0 + 1;
        const float ir0 = 1.f / g_rsum[row0];
        const float ir1 = 1.f / g_rsum[row1];
        const __half2* ev0 = reinterpret_cast<const __half2*>(g_e + (size_t)row0 * SD);
        const __half2* ev1 = reinterpret_cast<const __half2*>(g_e + (size_t)row1 * SD);
        float4* cv0 = reinterpret_cast<float4*>(conf + (size_t)row0 * SD);
        float4* cv1 = reinterpret_cast<float4*>(conf + (size_t)row1 * SD);
        float rcm0 = 0.f, rcm1 = 0.f;
        #pragma unroll
        for (int w = 0; w < 3; w++) {
            int i = tid + w * CTHR;
            if (i < NV4) {
                uint2 p0 = __ldcs(reinterpret_cast<const uint2*>(ev0 + 2 * i));
                uint2 p1 = __ldcs(reinterpret_cast<const uint2*>(ev1 + 2 * i));
                __half2 h00 = *reinterpret_cast<__half2*>(&p0.x);
                __half2 h01 = *reinterpret_cast<__half2*>(&p0.y);
                __half2 h10 = *reinterpret_cast<__half2*>(&p1.x);
                __half2 h11 = *reinterpret_cast<__half2*>(&p1.y);
                float2 e0a = __half22float2(h00), e0b = __half22float2(h01);
                float2 e1a = __half22float2(h10), e1b = __half22float2(h11);
                float4 ci = s_cinv[i];
                float4 c0, c1;
                c0.x = e0a.x * ci.x * ir0; c0.y = e0a.y * ci.y * ir0;
                c0.z = e0b.x * ci.z * ir0; c0.w = e0b.y * ci.w * ir0;
                c1.x = e1a.x * ci.x * ir1; c1.y = e1a.y * ci.y * ir1;
                c1.z = e1b.x * ci.z * ir1; c1.w = e1b.y * ci.w * ir1;
                __stcs(cv0 + i, c0);
                __stcs(cv1 + i, c1);
                rcm0 = fmaxf(rcm0, fmaxf(fmaxf(c0.x, c0.y), fmaxf(c0.z, c0.w)));
                rcm1 = fmaxf(rcm1, fmaxf(fmaxf(c1.x, c1.y), fmaxf(c1.z, c1.w)));
                cmax[w].x = fmaxf(cmax[w].x, fmaxf(c0.x, c1.x));
                cmax[w].y = fmaxf(cmax[w].y, fmaxf(c0.y, c1.y));
                cmax[w].z = fmaxf(cmax[w].z, fmaxf(c0.z, c1.z));
                cmax[w].w = fmaxf(cmax[w].w, fmaxf(c0.w, c1.w));
            }
        }
        rcm0 = warpMaxF(rcm0);
        rcm1 = warpMaxF(rcm1);
        if ((tid & 31) == 0) {
            atomicMax(&g_rcmax[row0], __float_as_int(rcm0));
            atomicMax(&g_rcmax[row1], __float_as_int(rcm1));
        }
    }
    #pragma unroll
    for (int w = 0; w < 3; w++) {
        int i = tid + w * CTHR;
        if (i < NV4) {
            int base = n * SD + i * 4;
            atomicMax(&g_ccmax[base + 0], __float_as_int(cmax[w].x));
            atomicMax(&g_ccmax[base + 1], __float_as_int(cmax[w].y));
            atomicMax(&g_ccmax[base + 2], __float_as_int(cmax[w].z));
            atomicMax(&g_ccmax[base + 3], __float_as_int(cmax[w].w));
        }
    }
}

// match extraction: warp per row, O(1) early-out; scans conf only for live rows
__global__ void __launch_bounds__(256) k_match(const float* __restrict__ conf,
                                               float* __restrict__ mmask,
                                               float* __restrict__ jids,
                                               float* __restrict__ mconf,
                                               const int* __restrict__ w0p,
                                               const int* __restrict__ w1p) {
    const int lane = threadIdx.x & 31;
    const int row = blockIdx.x * 8 + (threadIdx.x >> 5);
    const int n = row / LD;
    const int l = row % LD;
    const int w0c = *w0p;
    const int w1c = *w1p;

    const bool v0 = ((l / w0c) >= BORDER) && ((l % w0c) >= BORDER);
    const float rm = __int_as_float(g_rcmax[row]);
    const float* crow = conf + (size_t)row * SD;

    int best = 0x7fffffff;
    if (v0 && rm > THRESH) {               // ~never true for random features
        for (int s = lane; s < SD; s += 32) {
            float c = crow[s];
            if (c > THRESH && c == rm && c == __int_as_float(g_ccmax[n * SD + s])) {
                if (((s / w1c) >= BORDER) && ((s % w1c) >= BORDER)) best = min(best, s);
            }
        }
        best = warpMinI(best);
    }
    if (lane == 0) {
        bool match = (best != 0x7fffffff);
        int j = match ? best : 0;
        mmask[row] = match ? 1.f : 0.f;
        jids[row]  = (float)j;
        mconf[row] = match ? crow[j] : 0.f;
    }
}

// ---------------- launch ----------------
extern "C" void kernel_launch(void* const* d_in, const int* in_sizes, int n_in,
                              void* d_out, int out_size) {
    const float* f0 = (const float*)d_in[0];
    const float* f1 = (const float*)d_in[1];
    const int* w0 = (const int*)d_in[3];
    const int* w1 = (const int*)d_in[5];

    float* out = (float*)d_out;
    float* conf = out;
    const size_t NLS = (size_t)NB * LD * SD;
    float* mm = out + NLS;
    float* jj = mm + NB * LD;
    float* mc = jj + NB * LD;

    static int cfg_done = 0;
    if (!cfg_done) {
        cudaFuncSetAttribute(k_gemm_mma, cudaFuncAttributeMaxDynamicSharedMemorySize, DSMEM_B);
        cfg_done = 1;
    }

    k_convert<<<(NB * LD * (CD / 4) + 255) / 256, 256>>>(f0, f1);
    dim3 gg((SD + TN - 1) / TN, (LD + TM - 1) / TM, NB);
    k_gemm_mma<<<gg, 256, DSMEM_B>>>();
    k_conf<<<NB * LD / CROWS, CTHR>>>(conf);
    k_match<<<NB * LD / 8, 256>>>(conf, mm, jj, mc, w0, w1);
}

// round 17
// speedup vs baseline: 1.3902x; 1.2698x over previous
#include <cuda_runtime.h>
#include <cuda_fp16.h>
#include <cstdint>

#define NB 2
#define LD 4800
#define SD 4800
#define CD 256
#define TEMPER 0.1f
#define THRESH 0.2f
#define BORDER 2

#define KTOT 512          // fp16 2-term split: A_cat=[Ah|Al], B_cat=[Bh|Bh]
#define TM 128
#define TN 128
#define KC 64
#define NCHUNK (KTOT / KC)      // 8
#define ROWB 144
#define ABUF_B (TM * ROWB)
#define BBUF_B (TN * ROWB)
#define STG_B (ABUF_B + BBUF_B)
#define NSTG 3
#define DSMEM_B (NSTG * STG_B)

// ---------------- scratch ----------------
__device__ __half g_e[(size_t)NB * LD * SD];      // exp(2*sim) in fp16 (92 MB)
__device__ __align__(128) __half g_acat[(size_t)NB * LD * KTOT];   // 9.8 MB
__device__ __align__(128) __half g_bcat[(size_t)NB * SD * KTOT];   // 9.8 MB
__device__ float g_rsum[NB * LD];
__device__ float g_csum[NB * SD];
__device__ int g_rcmax[NB * LD];                  // conf row max bits
__device__ int g_ccmax[NB * SD];                  // conf col max bits

// ---------------- PTX helpers ----------------
__device__ __forceinline__ uint32_t s2u(const void* p) {
    uint32_t a;
    asm("{ .reg .u64 t; cvta.to.shared.u64 t, %1; cvt.u32.u64 %0, t; }" : "=r"(a) : "l"(p));
    return a;
}
__device__ __forceinline__ void ldsm_x4(uint32_t& r0, uint32_t& r1, uint32_t& r2, uint32_t& r3,
                                        uint32_t addr) {
    asm volatile("ldmatrix.sync.aligned.m8n8.x4.shared.b16 {%0,%1,%2,%3}, [%4];"
                 : "=r"(r0), "=r"(r1), "=r"(r2), "=r"(r3) : "r"(addr));
}
__device__ __forceinline__ void mma_f16(float* d, const uint32_t* a, const uint32_t* b) {
    asm volatile(
        "mma.sync.aligned.m16n8k16.row.col.f32.f16.f16.f32 "
        "{%0,%1,%2,%3}, {%4,%5,%6,%7}, {%8,%9}, {%0,%1,%2,%3};"
        : "+f"(d[0]), "+f"(d[1]), "+f"(d[2]), "+f"(d[3])
        : "r"(a[0]), "r"(a[1]), "r"(a[2]), "r"(a[3]), "r"(b[0]), "r"(b[1]));
}
__device__ __forceinline__ void cp16(uint32_t dst, const void* src, bool pred) {
    int sz = pred ? 16 : 0;
    asm volatile("cp.async.cg.shared.global [%0], [%1], 16, %2;"
                 :: "r"(dst), "l"(src), "r"(sz) : "memory");
}
#define CP_COMMIT() asm volatile("cp.async.commit_group;" ::: "memory")
#define CP_WAIT1()  asm volatile("cp.async.wait_group 1;" ::: "memory")
#define CP_WAIT0()  asm volatile("cp.async.wait_group 0;" ::: "memory")

__device__ __forceinline__ float warpMaxF(float v) {
    #pragma unroll
    for (int o = 16; o; o >>= 1) v = fmaxf(v, __shfl_xor_sync(0xffffffffu, v, o));
    return v;
}
__device__ __forceinline__ int warpMinI(int v) {
    #pragma unroll
    for (int o = 16; o; o >>= 1) v = min(v, __shfl_xor_sync(0xffffffffu, v, o));
    return v;
}

// fp32x4 -> packed fp16 hi/lo pairs (hi = rn(x), lo = rn(x - hi))
__device__ __forceinline__ void split4h(const float4& x, uint2& hp, uint2& lp) {
    __half h0 = __float2half_rn(x.x), h1 = __float2half_rn(x.y);
    __half h2 = __float2half_rn(x.z), h3 = __float2half_rn(x.w);
    __half l0 = __float2half_rn(x.x - __half2float(h0));
    __half l1 = __float2half_rn(x.y - __half2float(h1));
    __half l2 = __float2half_rn(x.z - __half2float(h2));
    __half l3 = __float2half_rn(x.w - __half2float(h3));
    __half2 a01 = __halves2half2(h0, h1), a23 = __halves2half2(h2, h3);
    __half2 b01 = __halves2half2(l0, l1), b23 = __halves2half2(l2, l3);
    hp.x = *reinterpret_cast<uint32_t*>(&a01); hp.y = *reinterpret_cast<uint32_t*>(&a23);
    lp.x = *reinterpret_cast<uint32_t*>(&b01); lp.y = *reinterpret_cast<uint32_t*>(&b23);
}

// ---------------- kernels ----------------
// convert + fused stats-init
__global__ void __launch_bounds__(256) k_convert(const float* __restrict__ f0,
                                                 const float* __restrict__ f1) {
    int idx = blockIdx.x * blockDim.x + threadIdx.x;
    if (idx < NB * SD) {
        g_rsum[idx] = 0.f;
        g_csum[idx] = 0.f;
        g_rcmax[idx] = 0;
        g_ccmax[idx] = 0;
    }
    if (idx >= NB * LD * (CD / 4)) return;
    int row = idx / (CD / 4);
    int c = (idx % (CD / 4)) * 4;
    {
        float4 x = *reinterpret_cast<const float4*>(f0 + (size_t)row * CD + c);
        uint2 hp, lp; split4h(x, hp, lp);
        __half* r = g_acat + (size_t)row * KTOT;
        *reinterpret_cast<uint2*>(r + c) = hp;        // Ah
        *reinterpret_cast<uint2*>(r + CD + c) = lp;   // Al
    }
    {
        float4 x = *reinterpret_cast<const float4*>(f1 + (size_t)row * CD + c);
        uint2 hp, lp; split4h(x, hp, lp);
        __half* r = g_bcat + (size_t)row * KTOT;
        *reinterpret_cast<uint2*>(r + c) = hp;        // Bh
        *reinterpret_cast<uint2*>(r + CD + c) = hp;   // Bh (paired with Al)
    }
}

// HMMA fp16 GEMM 128x128, K=512 -> fp16 exp(2*sim) + fused stats
__global__ void __launch_bounds__(256, 2) k_gemm_mma() {
    extern __shared__ char smem[];
    const int tid = threadIdx.x;
    const int wid = tid >> 5;
    const int lane = tid & 31;
    const int warp_m = wid & 1;
    const int warp_n = wid >> 1;

    const int b  = blockIdx.z;
    const int m0 = blockIdx.y * TM;
    const int n0 = blockIdx.x * TN;
    const int mrem = min(TM, LD - m0);
    const int nrem = min(TN, SD - n0);

    const __half* Abase = g_acat + (size_t)(b * LD + m0) * KTOT;
    const __half* Bbase = g_bcat + (size_t)(b * SD + n0) * KTOT;
    const uint32_t sbase = s2u(smem);

    float acc[4][4][4];
    #pragma unroll
    for (int i = 0; i < 4; i++)
        #pragma unroll
        for (int j = 0; j < 4; j++)
            #pragma unroll
            for (int q = 0; q < 4; q++) acc[i][j][q] = 0.f;

    auto issue = [&](int chunk, int buf) {
        const int k0 = chunk * KC;
        const uint32_t sA = sbase + buf * STG_B;
        const uint32_t sB = sA + ABUF_B;
        #pragma unroll
        for (int i = 0; i < 4; i++) {
            int f = tid + i * 256;
            int row = f >> 3, q = f & 7;
            bool pa = row < mrem;
            int ra = pa ? row : 0;
            cp16(sA + row * ROWB + q * 16, Abase + (size_t)ra * KTOT + k0 + q * 8, pa);
            bool pb = row < nrem;
            int rb = pb ? row : 0;
            cp16(sB + row * ROWB + q * 16, Bbase + (size_t)rb * KTOT + k0 + q * 8, pb);
        }
        CP_COMMIT();
    };

    issue(0, 0);
    issue(1, 1);

    const int g = lane >> 3;
    const int lr = lane & 7;

    for (int s = 0; s < NCHUNK; s++) {
        if (s == NCHUNK - 1) { CP_WAIT0(); } else { CP_WAIT1(); }
        __syncthreads();
        const int buf = s % NSTG;
        const uint32_t sA = sbase + buf * STG_B;
        const uint32_t sB = sA + ABUF_B;
        if (s + 2 < NCHUNK) issue(s + 2, (s + 2) % NSTG);

        #pragma unroll
        for (int ks = 0; ks < KC / 16; ks++) {
            const int kb = ks * 16;
            uint32_t a[4][4];
            #pragma unroll
            for (int mi = 0; mi < 4; mi++) {
                uint32_t addr = sA + (uint32_t)((warp_m * 64 + mi * 16 + (g & 1) * 8 + lr) * ROWB
                                                + (kb + (g >> 1) * 8) * 2);
                ldsm_x4(a[mi][0], a[mi][1], a[mi][2], a[mi][3], addr);
            }
            uint32_t bfr[4][2];
            #pragma unroll
            for (int p = 0; p < 2; p++) {
                uint32_t r0, r1, r2, r3;
                uint32_t addr = sB + (uint32_t)((warp_n * 32 + p * 16 + (g >> 1) * 8 + lr) * ROWB
                                                + (kb + (g & 1) * 8) * 2);
                ldsm_x4(r0, r1, r2, r3, addr);
                bfr[p * 2 + 0][0] = r0; bfr[p * 2 + 0][1] = r1;
                bfr[p * 2 + 1][0] = r2; bfr[p * 2 + 1][1] = r3;
            }
            #pragma unroll
            for (int mi = 0; mi < 4; mi++)
                #pragma unroll
                for (int ni = 0; ni < 4; ni++)
                    mma_f16(acc[mi][ni], a[mi], bfr[ni]);
        }
        // trailing __syncthreads removed (verified round 14)
    }

    const float sc = 1.0f / ((float)CD * TEMPER);
    const int qrow = lane >> 2;
    const int qcol = (lane & 3) * 2;

    float rowsum[4][2];
    float colsum[4][2];
    #pragma unroll
    for (int i = 0; i < 4; i++) { rowsum[i][0] = rowsum[i][1] = 0.f; colsum[i][0] = colsum[i][1] = 0.f; }

    #pragma unroll
    for (int mi = 0; mi < 4; mi++) {
        #pragma unroll
        for (int half = 0; half < 2; half++) {
            int lrow = warp_m * 64 + mi * 16 + half * 8 + qrow;
            bool rv = lrow < mrem;
            __half* dst = g_e + ((size_t)(b * LD) + m0 + lrow) * SD + n0;
            #pragma unroll
            for (int ni = 0; ni < 4; ni++) {
                int lcol = warp_n * 32 + ni * 8 + qcol;
                bool cv = lcol < nrem;
                float vx = acc[mi][ni][half * 2 + 0] * sc;
                float vy = acc[mi][ni][half * 2 + 1] * sc;
                float ex = (rv && cv) ? __expf(vx) : 0.f;
                float ey = (rv && cv) ? __expf(vy) : 0.f;
                if (rv && cv) {
                    __half2 h = __floats2half2_rn(ex * ex, ey * ey);  // exp(2*sim)
                    *reinterpret_cast<__half2*>(dst + lcol) = h;
                }
                rowsum[mi][half] += ex + ey;
                colsum[ni][0] += ex;
                colsum[ni][1] += ey;
            }
        }
    }
    #pragma unroll
    for (int mi = 0; mi < 4; mi++) {
        #pragma unroll
        for (int half = 0; half < 2; half++) {
            float r = rowsum[mi][half];
            r += __shfl_xor_sync(0xffffffffu, r, 1);
            r += __shfl_xor_sync(0xffffffffu, r, 2);
            if ((lane & 3) == 0) {
                int lrow = warp_m * 64 + mi * 16 + half * 8 + qrow;
                if (lrow < mrem) atomicAdd(&g_rsum[b * LD + m0 + lrow], r);
            }
        }
    }
    #pragma unroll
    for (int ni = 0; ni < 4; ni++) {
        #pragma unroll
        for (int c = 0; c < 2; c++) {
            float v = colsum[ni][c];
            v += __shfl_xor_sync(0xffffffffu, v, 4);
            v += __shfl_xor_sync(0xffffffffu, v, 8);
            v += __shfl_xor_sync(0xffffffffu, v, 16);
            if (lane < 4) {
                int lcol = warp_n * 32 + ni * 8 + qcol + c;
                if (lcol < nrem) atomicAdd(&g_csum[b * SD + n0 + lcol], v);
            }
        }
    }
}

// conf = e * inv_rs * inv_cs; pure fmax row/col maxes
#define CROWS 16
#define NV4 (SD / 4)              // 1200 slots of 4 elements
#define CTHR 512
__global__ void __launch_bounds__(CTHR, 3) k_conf(float* __restrict__ conf) {
    __shared__ float4 s_cinv[NV4];    // 19.2 KB
    const int r0 = blockIdx.x * CROWS;
    const int n = r0 / LD;
    const int tid = threadIdx.x;

    for (int i = tid; i < NV4; i += CTHR) {
        float4 cs = *reinterpret_cast<const float4*>(&g_csum[n * SD + i * 4]);
        float4 ci;
        ci.x = 1.f / cs.x; ci.y = 1.f / cs.y; ci.z = 1.f / cs.z; ci.w = 1.f / cs.w;
        s_cinv[i] = ci;
    }
    __syncthreads();

    float4 cmax[3];
    #pragma unroll
    for (int w = 0; w < 3; w++) cmax[w] = make_float4(0.f, 0.f, 0.f, 0.f);

    for (int rr = 0; rr < CROWS; rr += 2) {
        const int row0 = r0 + rr;
        const int row1 = row0 + 1;
        const float ir0 = 1.f / g_rsum[row0];
        const float ir1 = 1.f / g_rsum[row1];
        const __half2* ev0 = reinterpret_cast<const __half2*>(g_e + (size_t)row0 * SD);
        const __half2* ev1 = reinterpret_cast<const __half2*>(g_e + (size_t)row1 * SD);
        float4* cv0 = reinterpret_cast<float4*>(conf + (size_t)row0 * SD);
        float4* cv1 = reinterpret_cast<float4*>(conf + (size_t)row1 * SD);
        float rcm0 = 0.f, rcm1 = 0.f;
        #pragma unroll
        for (int w = 0; w < 3; w++) {
            int i = tid + w * CTHR;
            if (i < NV4) {
                uint2 p0 = __ldcs(reinterpret_cast<const uint2*>(ev0 + 2 * i));
                uint2 p1 = __ldcs(reinterpret_cast<const uint2*>(ev1 + 2 * i));
                __half2 h00 = *reinterpret_cast<__half2*>(&p0.x);
                __half2 h01 = *reinterpret_cast<__half2*>(&p0.y);
                __half2 h10 = *reinterpret_cast<__half2*>(&p1.x);
                __half2 h11 = *reinterpret_cast<__half2*>(&p1.y);
                float2 e0a = __half22float2(h00), e0b = __half22float2(h01);
                float2 e1a = __half22float2(h10), e1b = __half22float2(h11);
                float4 ci = s_cinv[i];
                float4 c0, c1;
                c0.x = e0a.x * ci.x * ir0; c0.y = e0a.y * ci.y * ir0;
                c0.z = e0b.x * ci.z * ir0; c0.w = e0b.y * ci.w * ir0;
                c1.x = e1a.x * ci.x * ir1; c1.y = e1a.y * ci.y * ir1;
                c1.z = e1b.x * ci.z * ir1; c1.w = e1b.y * ci.w * ir1;
                __stcs(cv0 + i, c0);
                __stcs(cv1 + i, c1);
                rcm0 = fmaxf(rcm0, fmaxf(fmaxf(c0.x, c0.y), fmaxf(c0.z, c0.w)));
                rcm1 = fmaxf(rcm1, fmaxf(fmaxf(c1.x, c1.y), fmaxf(c1.z, c1.w)));
                cmax[w].x = fmaxf(cmax[w].x, fmaxf(c0.x, c1.x));
                cmax[w].y = fmaxf(cmax[w].y, fmaxf(c0.y, c1.y));
                cmax[w].z = fmaxf(cmax[w].z, fmaxf(c0.z, c1.z));
                cmax[w].w = fmaxf(cmax[w].w, fmaxf(c0.w, c1.w));
            }
        }
        rcm0 = warpMaxF(rcm0);
        rcm1 = warpMaxF(rcm1);
        if ((tid & 31) == 0) {
            atomicMax(&g_rcmax[row0], __float_as_int(rcm0));
            atomicMax(&g_rcmax[row1], __float_as_int(rcm1));
        }
    }
    #pragma unroll
    for (int w = 0; w < 3; w++) {
        int i = tid + w * CTHR;
        if (i < NV4) {
            int base = n * SD + i * 4;
            atomicMax(&g_ccmax[base + 0], __float_as_int(cmax[w].x));
            atomicMax(&g_ccmax[base + 1], __float_as_int(cmax[w].y));
            atomicMax(&g_ccmax[base + 2], __float_as_int(cmax[w].z));
            atomicMax(&g_ccmax[base + 3], __float_as_int(cmax[w].w));
        }
    }
}

// match extraction: warp per row, O(1) early-out
__global__ void __launch_bounds__(256) k_match(const float* __restrict__ conf,
                                               float* __restrict__ mmask,
                                               float* __restrict__ jids,
                                               float* __restrict__ mconf,
                                               const int* __restrict__ w0p,
                                               const int* __restrict__ w1p) {
    const int lane = threadIdx.x & 31;
    const int row = blockIdx.x * 8 + (threadIdx.x >> 5);
    const int n = row / LD;
    const int l = row % LD;
    const int w0c = *w0p;
    const int w1c = *w1p;

    const bool v0 = ((l / w0c) >= BORDER) && ((l % w0c) >= BORDER);
    const float rm = __int_as_float(g_rcmax[row]);
    const float* crow = conf + (size_t)row * SD;

    int best = 0x7fffffff;
    if (v0 && rm > THRESH) {
        for (int s = lane; s < SD; s += 32) {
            float c = crow[s];
            if (c > THRESH && c == rm && c == __int_as_float(g_ccmax[n * SD + s])) {
                if (((s / w1c) >= BORDER) && ((s % w1c) >= BORDER)) best = min(best, s);
            }
        }
        best = warpMinI(best);
    }
    if (lane == 0) {
        bool match = (best != 0x7fffffff);
        int j = match ? best : 0;
        mmask[row] = match ? 1.f : 0.f;
        jids[row]  = (float)j;
        mconf[row] = match ? crow[j] : 0.f;
    }
}

// ---------------- launch ----------------
extern "C" void kernel_launch(void* const* d_in, const int* in_sizes, int n_in,
                              void* d_out, int out_size) {
    const float* f0 = (const float*)d_in[0];
    const float* f1 = (const float*)d_in[1];
    const int* w0 = (const int*)d_in[3];
    const int* w1 = (const int*)d_in[5];

    float* out = (float*)d_out;
    float* conf = out;
    const size_t NLS = (size_t)NB * LD * SD;
    float* mm = out + NLS;
    float* jj = mm + NB * LD;
    float* mc = jj + NB * LD;

    static int cfg_done = 0;
    if (!cfg_done) {
        cudaFuncSetAttribute(k_gemm_mma, cudaFuncAttributeMaxDynamicSharedMemorySize, DSMEM_B);
        cfg_done = 1;
    }

    k_convert<<<(NB * LD * (CD / 4) + 255) / 256, 256>>>(f0, f1);
    dim3 gg((SD + TN - 1) / TN, (LD + TM - 1) / TM, NB);
    k_gemm_mma<<<gg, 256, DSMEM_B>>>();
    k_conf<<<NB * LD / CROWS, CTHR>>>(conf);
    k_match<<<NB * LD / 8, 256>>>(conf, mm, jj, mc, w0, w1);
}